// round 13
// baseline (speedup 1.0000x reference)
#include <cuda_runtime.h>
#include <cuda_bf16.h>
#include <cstdint>

// IoU kernel: elementwise over N boxes, A=5 anchors.
// Inputs (metadata order):
//   d_in[0]: cell_nos  int32  [N,2]
//   d_in[1]: output    float  [N,5,5]
//   d_in[2]: target    float  [N,5]
// Output: float [N,5]
//
// Persistent kernel, 2 CTAs per SM, 3-stage TMA input pipeline with two
// DECOUPLED ping-pong result buffers:
//   - load issue depends only on compute having consumed stage s
//     (issue tile k+3 immediately after the post-compute barrier)
//   - store backpressure (wait_group 1 -> store k-2 done) sits BEFORE
//     compute, with 2 iterations of slack -- off the load-issue path
//   - 2 CTAs/SM overlap each other's serial t0 sections and barriers,
//     keeping ~4 x 32KB bulk loads in flight per SM with no wave
//     transitions.

#define YI 20.0f
#define BPB 256           // boxes per tile == threads per block
#define A 5               // anchors
#define S_STAGES 3        // input stages
#define CTAS_PER_SM 2

#define OUT_BYTES (BPB * 25 * 4)   // 25600
#define TGT_BYTES (BPB * 5 * 4)    //  5120
#define CEL_BYTES (BPB * 2 * 4)    //  2048
#define STAGE_BYTES (OUT_BYTES + TGT_BYTES + CEL_BYTES)   // 32768
#define RES_BYTES  TGT_BYTES                              //  5120
#define SMEM_TOTAL (S_STAGES * STAGE_BYTES + 2 * RES_BYTES)  // 108544

extern __shared__ char dsm[];

__device__ __forceinline__ void mbar_wait(uint32_t mbar_a, uint32_t parity) {
    uint32_t done;
    asm volatile(
        "{\n\t"
        ".reg .pred p;\n\t"
        "mbarrier.try_wait.parity.acquire.cta.shared::cta.b64 p, [%1], %2;\n\t"
        "selp.b32 %0, 1, 0, p;\n\t"
        "}"
        : "=r"(done) : "r"(mbar_a), "r"(parity) : "memory");
    if (!done) {
        asm volatile(
            "{\n\t"
            ".reg .pred P1;\n\t"
            "WAIT_LOOP_%=:\n\t"
            "mbarrier.try_wait.parity.acquire.cta.shared::cta.b64 P1, [%0], %1, 0x989680;\n\t"
            "@P1 bra.uni WAIT_DONE_%=;\n\t"
            "bra.uni WAIT_LOOP_%=;\n\t"
            "WAIT_DONE_%=:\n\t"
            "}"
            :: "r"(mbar_a), "r"(parity) : "memory");
    }
}

__global__ __launch_bounds__(BPB, CTAS_PER_SM) void iou_kernel(
    const int* __restrict__ cell_nos,
    const float* __restrict__ output,
    const float* __restrict__ target,
    float* __restrict__ res,
    int n)
{
    __shared__ alignas(8) unsigned long long mbar[S_STAGES];

    const int tid = threadIdx.x;
    const int G   = gridDim.x;
    const int bid = blockIdx.x;
    const int ntiles = n / BPB;

    const uint32_t dsm_a   = (uint32_t)__cvta_generic_to_shared(dsm);
    const uint32_t mbar0_a = (uint32_t)__cvta_generic_to_shared(&mbar[0]);
    float* resbuf[2];
    resbuf[0] = reinterpret_cast<float*>(dsm + S_STAGES * STAGE_BYTES);
    resbuf[1] = reinterpret_cast<float*>(dsm + S_STAGES * STAGE_BYTES + RES_BYTES);
    uint32_t resbuf_a[2];
    resbuf_a[0] = dsm_a + S_STAGES * STAGE_BYTES;
    resbuf_a[1] = dsm_a + S_STAGES * STAGE_BYTES + RES_BYTES;

    if (tid == 0) {
        #pragma unroll
        for (int s = 0; s < S_STAGES; s++) {
            asm volatile("mbarrier.init.shared::cta.b64 [%0], %1;"
                         :: "r"(mbar0_a + s * 8), "r"(1) : "memory");
        }
        asm volatile("fence.proxy.async.shared::cta;" ::: "memory");
    }
    __syncthreads();

    // Tiles owned by this CTA: bid, bid+G, bid+2G, ...
    const int my_nt = (ntiles > bid) ? ((ntiles - 1 - bid) / G + 1) : 0;

    // t0-only: issue the three bulk loads for owned-tile k into stage s.
    auto issue = [&](int k, int s) {
        const size_t tbase = ((size_t)bid + (size_t)k * G) * BPB;
        const uint32_t mb = mbar0_a + (uint32_t)s * 8;
        const uint32_t sb = dsm_a + (uint32_t)s * STAGE_BYTES;
        asm volatile("mbarrier.arrive.expect_tx.shared::cta.b64 _, [%0], %1;"
                     :: "r"(mb), "r"((uint32_t)STAGE_BYTES) : "memory");
        asm volatile("cp.async.bulk.shared::cta.global.mbarrier::complete_tx::bytes "
                     "[%0], [%1], %2, [%3];"
                     :: "r"(sb), "l"(output + tbase * 25),
                        "r"((uint32_t)OUT_BYTES), "r"(mb) : "memory");
        asm volatile("cp.async.bulk.shared::cta.global.mbarrier::complete_tx::bytes "
                     "[%0], [%1], %2, [%3];"
                     :: "r"(sb + OUT_BYTES), "l"(target + tbase * 5),
                        "r"((uint32_t)TGT_BYTES), "r"(mb) : "memory");
        asm volatile("cp.async.bulk.shared::cta.global.mbarrier::complete_tx::bytes "
                     "[%0], [%1], %2, [%3];"
                     :: "r"(sb + OUT_BYTES + TGT_BYTES), "l"(cell_nos + tbase * 2),
                        "r"((uint32_t)CEL_BYTES), "r"(mb) : "memory");
    };

    // Prologue: fill all 3 stages.
    if (tid == 0) {
        const int npro = (my_nt < S_STAGES) ? my_nt : S_STAGES;
        for (int k = 0; k < npro; k++) issue(k, k);
    }

    int s = 0, epoch = 0;   // stage = k % S; parity = (k / S) & 1
    for (int k = 0; k < my_nt; k++) {
        const uint32_t mb = mbar0_a + (uint32_t)s * 8;
        char* sb = dsm + (size_t)s * STAGE_BYTES;
        float* s_out  = reinterpret_cast<float*>(sb);
        float* s_tgt  = reinterpret_cast<float*>(sb + OUT_BYTES);
        int*   s_cell = reinterpret_cast<int*>(sb + OUT_BYTES + TGT_BYTES);
        float* rbuf   = resbuf[k & 1];

        // Wait for tile k's data in stage s.
        mbar_wait(mb, (uint32_t)(epoch & 1));

        // Store backpressure: before overwriting resbuf[k&1], store k-2 (its
        // previous user) must be done. Committed groups so far: 0..k-1;
        // wait_group 1 leaves at most the newest (k-1) outstanding.
        if (tid == 0 && k >= 2) {
            asm volatile("cp.async.bulk.wait_group 1;" ::: "memory");
        }
        __syncthreads();

        // ---- compute tile k from stage s into resbuf[k&1] ----
        {
            const float ci = (float)s_cell[2 * tid]     * YI + YI * 0.5f;
            const float cj = (float)s_cell[2 * tid + 1] * YI + YI * 0.5f;

            const float* t = &s_tgt[5 * tid];
            const float g_h = t[3] * YI, g_w = t[4] * YI;
            const float gxc = ci + t[1] * YI;
            const float gyc = cj + t[2] * YI;
            const float gx1 = gyc - g_w * 0.5f;
            const float gy1 = gxc - g_h * 0.5f;
            const float gx2 = gyc + g_w * 0.5f;
            const float gy2 = gxc + g_h * 0.5f;
            const float area_g = (gx2 - gx1) * (gy2 - gy1);

            #pragma unroll
            for (int a = 0; a < A; a++) {
                const float* o = &s_out[25 * tid + 5 * a];
                const float p_h = o[3] * YI, p_w = o[4] * YI;
                const float pxc = ci + o[1] * YI;
                const float pyc = cj + o[2] * YI;
                const float px1 = pyc - p_w * 0.5f;
                const float py1 = pxc - p_h * 0.5f;
                const float px2 = pyc + p_w * 0.5f;
                const float py2 = pxc + p_h * 0.5f;
                const float area_p = (px2 - px1) * (py2 - py1);

                const float lx = fmaxf(px1, gx1);
                const float ly = fmaxf(py1, gy1);
                const float rx = fminf(px2, gx2);
                const float ry = fminf(py2, gy2);
                const float iw = fmaxf(rx - lx, 0.0f);
                const float ih = fmaxf(ry - ly, 0.0f);
                const float inter = iw * ih;
                const float uni = area_p + area_g - inter;
                rbuf[5 * tid + a] = __fdividef(inter, uni);
            }
        }
        __syncthreads();   // results complete; stage s inputs fully consumed

        if (tid == 0) {
            // Drain tile k's results, then IMMEDIATELY reuse stage s for tile
            // k+3 (load issue independent of store completion).
            const size_t tbase = ((size_t)bid + (size_t)k * G) * BPB;
            asm volatile("fence.proxy.async.shared::cta;" ::: "memory");
            asm volatile("cp.async.bulk.global.shared::cta.bulk_group [%0], [%1], %2;"
                         :: "l"(res + tbase * 5), "r"(resbuf_a[k & 1]),
                            "r"((uint32_t)RES_BYTES) : "memory");
            asm volatile("cp.async.bulk.commit_group;" ::: "memory");
            if (k + S_STAGES < my_nt) issue(k + S_STAGES, s);
        }

        if (++s == S_STAGES) { s = 0; epoch ^= 1; }
    }

    // Ensure all bulk stores complete before exit.
    if (tid == 0) {
        asm volatile("cp.async.bulk.wait_group 0;" ::: "memory");
    }

    // Tail boxes (n % BPB != 0): direct scalar path (never taken at bench
    // shape N=4,000,000 = 15625*256). Handled by the last CTA.
    const int rem_base = ntiles * BPB;
    if (bid == G - 1 && rem_base + tid < n) {
        const int box = rem_base + tid;
        const float ci = (float)cell_nos[2 * box]     * YI + YI * 0.5f;
        const float cj = (float)cell_nos[2 * box + 1] * YI + YI * 0.5f;
        const float* t = target + (size_t)box * 5;
        const float g_h = t[3] * YI, g_w = t[4] * YI;
        const float gxc = ci + t[1] * YI;
        const float gyc = cj + t[2] * YI;
        const float gx1 = gyc - g_w * 0.5f;
        const float gy1 = gxc - g_h * 0.5f;
        const float gx2 = gyc + g_w * 0.5f;
        const float gy2 = gxc + g_h * 0.5f;
        const float area_g = (gx2 - gx1) * (gy2 - gy1);
        #pragma unroll
        for (int a = 0; a < A; a++) {
            const float* o = output + (size_t)box * 25 + 5 * a;
            const float p_h = o[3] * YI, p_w = o[4] * YI;
            const float pxc = ci + o[1] * YI;
            const float pyc = cj + o[2] * YI;
            const float px1 = pyc - p_w * 0.5f;
            const float py1 = pxc - p_h * 0.5f;
            const float px2 = pyc + p_w * 0.5f;
            const float py2 = pxc + p_h * 0.5f;
            const float area_p = (px2 - px1) * (py2 - py1);
            const float lx = fmaxf(px1, gx1);
            const float ly = fmaxf(py1, gy1);
            const float rx = fminf(px2, gx2);
            const float ry = fminf(py2, gy2);
            const float iw = fmaxf(rx - lx, 0.0f);
            const float ih = fmaxf(ry - ly, 0.0f);
            const float inter = iw * ih;
            res[(size_t)box * 5 + a] = __fdividef(inter, area_p + area_g - inter);
        }
    }
}

extern "C" void kernel_launch(void* const* d_in, const int* in_sizes, int n_in,
                              void* d_out, int out_size) {
    const int*   cell_nos = (const int*)d_in[0];
    const float* output   = (const float*)d_in[1];
    const float* target   = (const float*)d_in[2];
    float*       res      = (float*)d_out;

    const int n = in_sizes[0] / 2;  // cell_nos is [N,2]
    const int ntiles = n / BPB;

    // Identical API sequence on every call (no static guards — harness rule).
    int nsm = 0;
    if (cudaDeviceGetAttribute(&nsm, cudaDevAttrMultiProcessorCount, 0)
            != cudaSuccess || nsm <= 0)
        nsm = 148;  // conservative fallback
    cudaFuncSetAttribute(iou_kernel,
                         cudaFuncAttributeMaxDynamicSharedMemorySize,
                         SMEM_TOTAL);

    // 2 persistent CTAs per SM (108.5KB smem each; 217KB/SM <= 228KB).
    int grid = nsm * CTAS_PER_SM;
    if (grid > ntiles) grid = (ntiles > 0) ? ntiles : 1;

    iou_kernel<<<grid, BPB, SMEM_TOTAL>>>(cell_nos, output, target, res, n);
}

// round 14
// speedup vs baseline: 1.0394x; 1.0394x over previous
#include <cuda_runtime.h>
#include <cuda_bf16.h>
#include <cstdint>

// IoU kernel: elementwise over N boxes, A=5 anchors.
// Inputs (metadata order):
//   d_in[0]: cell_nos  int32  [N,2]
//   d_in[1]: output    float  [N,5,5]
//   d_in[2]: target    float  [N,5]
// Output: float [N,5]
//
// One-shot CTA swarm (R8 architecture) + 2 tiles per CTA, internally
// double-buffered:
//   - t0 inits 2 mbars, fences, and issues BOTH tiles' bulk loads before the
//     first barrier (early issue; tile1 load guaranteed outstanding during
//     tile0 compute/store)
//   - per tile: wait mbar -> compute (results overwrite s_tgt in place) ->
//     barrier -> bulk store commit; wait_group 0 only once at CTA exit
//   - 64KB smem/CTA -> 3 CTAs/SM -> 192KB front-loaded in-flight per SM,
//     same as R8 but half the per-CTA fixed costs.

#define YI 20.0f
#define BPB 256           // boxes per tile == threads per block
#define A 5               // anchors

#define OUT_BYTES (BPB * 25 * 4)   // 25600
#define TGT_BYTES (BPB * 5 * 4)    //  5120 (doubles as result buffer)
#define CEL_BYTES (BPB * 2 * 4)    //  2048
#define STAGE_BYTES (OUT_BYTES + TGT_BYTES + CEL_BYTES)   // 32768

__device__ __forceinline__ void mbar_wait(uint32_t mbar_a) {
    uint32_t done;
    asm volatile(
        "{\n\t"
        ".reg .pred p;\n\t"
        "mbarrier.try_wait.parity.acquire.cta.shared::cta.b64 p, [%1], 0;\n\t"
        "selp.b32 %0, 1, 0, p;\n\t"
        "}"
        : "=r"(done) : "r"(mbar_a) : "memory");
    if (!done) {
        asm volatile(
            "{\n\t"
            ".reg .pred P1;\n\t"
            "WAIT_LOOP_%=:\n\t"
            "mbarrier.try_wait.parity.acquire.cta.shared::cta.b64 P1, [%0], 0, 0x989680;\n\t"
            "@P1 bra.uni WAIT_DONE_%=;\n\t"
            "bra.uni WAIT_LOOP_%=;\n\t"
            "WAIT_DONE_%=:\n\t"
            "}"
            :: "r"(mbar_a) : "memory");
    }
}

__global__ __launch_bounds__(BPB) void iou_kernel(
    const int* __restrict__ cell_nos,
    const float* __restrict__ output,
    const float* __restrict__ target,
    float* __restrict__ res,
    int n)
{
    __shared__ alignas(16) char stage[2][STAGE_BYTES];
    __shared__ alignas(8)  unsigned long long mbar[2];

    const int tid = threadIdx.x;
    const int ntiles = n / BPB;
    const int t0_idx = 2 * blockIdx.x;       // first tile
    const int nt = (t0_idx + 2 <= ntiles) ? 2 : (ntiles - t0_idx);  // 1 or 2

    const uint32_t mbar0_a  = (uint32_t)__cvta_generic_to_shared(&mbar[0]);
    const uint32_t stage0_a = (uint32_t)__cvta_generic_to_shared(&stage[0][0]);

    // t0: init mbars, fence, and issue BOTH tiles' loads before the barrier.
    if (tid == 0) {
        asm volatile("mbarrier.init.shared::cta.b64 [%0], 1;"
                     :: "r"(mbar0_a) : "memory");
        asm volatile("mbarrier.init.shared::cta.b64 [%0], 1;"
                     :: "r"(mbar0_a + 8) : "memory");
        asm volatile("fence.proxy.async.shared::cta;" ::: "memory");
        #pragma unroll
        for (int q = 0; q < 2; q++) {
            if (q < nt) {
                const size_t tbase = (size_t)(t0_idx + q) * BPB;
                const uint32_t mb = mbar0_a + (uint32_t)q * 8;
                const uint32_t sb = stage0_a + (uint32_t)q * STAGE_BYTES;
                asm volatile("mbarrier.arrive.expect_tx.shared::cta.b64 _, [%0], %1;"
                             :: "r"(mb), "r"((uint32_t)STAGE_BYTES) : "memory");
                asm volatile("cp.async.bulk.shared::cta.global.mbarrier::complete_tx::bytes "
                             "[%0], [%1], %2, [%3];"
                             :: "r"(sb), "l"(output + tbase * 25),
                                "r"((uint32_t)OUT_BYTES), "r"(mb) : "memory");
                asm volatile("cp.async.bulk.shared::cta.global.mbarrier::complete_tx::bytes "
                             "[%0], [%1], %2, [%3];"
                             :: "r"(sb + OUT_BYTES), "l"(target + tbase * 5),
                                "r"((uint32_t)TGT_BYTES), "r"(mb) : "memory");
                asm volatile("cp.async.bulk.shared::cta.global.mbarrier::complete_tx::bytes "
                             "[%0], [%1], %2, [%3];"
                             :: "r"(sb + OUT_BYTES + TGT_BYTES), "l"(cell_nos + tbase * 2),
                                "r"((uint32_t)CEL_BYTES), "r"(mb) : "memory");
            }
        }
    }
    __syncthreads();   // mbar init visible to all threads before they poll

    #pragma unroll
    for (int q = 0; q < 2; q++) {
        if (q >= nt) break;
        char* sb = &stage[q][0];
        float* s_out  = reinterpret_cast<float*>(sb);
        float* s_tgt  = reinterpret_cast<float*>(sb + OUT_BYTES);
        int*   s_cell = reinterpret_cast<int*>(sb + OUT_BYTES + TGT_BYTES);

        mbar_wait(mbar0_a + (uint32_t)q * 8);

        // ---- compute tile q; results overwrite s_tgt in place ----
        {
            const float ci = (float)s_cell[2 * tid]     * YI + YI * 0.5f;
            const float cj = (float)s_cell[2 * tid + 1] * YI + YI * 0.5f;

            const float* t = &s_tgt[5 * tid];
            const float g_h = t[3] * YI, g_w = t[4] * YI;
            const float gxc = ci + t[1] * YI;
            const float gyc = cj + t[2] * YI;
            const float gx1 = gyc - g_w * 0.5f;
            const float gy1 = gxc - g_h * 0.5f;
            const float gx2 = gyc + g_w * 0.5f;
            const float gy2 = gxc + g_h * 0.5f;
            const float area_g = (gx2 - gx1) * (gy2 - gy1);

            float r[A];
            #pragma unroll
            for (int a = 0; a < A; a++) {
                const float* o = &s_out[25 * tid + 5 * a];
                const float p_h = o[3] * YI, p_w = o[4] * YI;
                const float pxc = ci + o[1] * YI;
                const float pyc = cj + o[2] * YI;
                const float px1 = pyc - p_w * 0.5f;
                const float py1 = pxc - p_h * 0.5f;
                const float px2 = pyc + p_w * 0.5f;
                const float py2 = pxc + p_h * 0.5f;
                const float area_p = (px2 - px1) * (py2 - py1);

                const float lx = fmaxf(px1, gx1);
                const float ly = fmaxf(py1, gy1);
                const float rx = fminf(px2, gx2);
                const float ry = fminf(py2, gy2);
                const float iw = fmaxf(rx - lx, 0.0f);
                const float ih = fmaxf(ry - ly, 0.0f);
                const float inter = iw * ih;
                const float uni = area_p + area_g - inter;
                r[a] = __fdividef(inter, uni);
            }
            // Thread tid overwrites exactly [5*tid, 5*tid+5), which only it
            // read above -> no cross-thread hazard.
            #pragma unroll
            for (int a = 0; a < A; a++) s_tgt[5 * tid + a] = r[a];
        }
        __syncthreads();   // results complete

        if (tid == 0) {
            const size_t tbase = (size_t)(t0_idx + q) * BPB;
            const uint32_t st_a = stage0_a + (uint32_t)q * STAGE_BYTES + OUT_BYTES;
            asm volatile("fence.proxy.async.shared::cta;" ::: "memory");
            asm volatile("cp.async.bulk.global.shared::cta.bulk_group [%0], [%1], %2;"
                         :: "l"(res + tbase * 5), "r"(st_a),
                            "r"((uint32_t)TGT_BYTES) : "memory");
            asm volatile("cp.async.bulk.commit_group;" ::: "memory");
        }
        // No barrier needed here: stage q is never touched again; stage q+1
        // work only depends on its own mbar.
    }

    // Drain both bulk stores before exit.
    if (tid == 0) {
        asm volatile("cp.async.bulk.wait_group 0;" ::: "memory");
    }

    // Tail boxes (n % BPB != 0): never taken at bench shape
    // (N=4,000,000 = 15625*256). Handled by CTA 0 for generality.
    const int rem_base = ntiles * BPB;
    if (blockIdx.x == 0 && rem_base + tid < n) {
        const int box = rem_base + tid;
        const float ci = (float)cell_nos[2 * box]     * YI + YI * 0.5f;
        const float cj = (float)cell_nos[2 * box + 1] * YI + YI * 0.5f;
        const float* t = target + (size_t)box * 5;
        const float g_h = t[3] * YI, g_w = t[4] * YI;
        const float gxc = ci + t[1] * YI;
        const float gyc = cj + t[2] * YI;
        const float gx1 = gyc - g_w * 0.5f;
        const float gy1 = gxc - g_h * 0.5f;
        const float gx2 = gyc + g_w * 0.5f;
        const float gy2 = gxc + g_h * 0.5f;
        const float area_g = (gx2 - gx1) * (gy2 - gy1);
        #pragma unroll
        for (int a = 0; a < A; a++) {
            const float* o = output + (size_t)box * 25 + 5 * a;
            const float p_h = o[3] * YI, p_w = o[4] * YI;
            const float pxc = ci + o[1] * YI;
            const float pyc = cj + o[2] * YI;
            const float px1 = pyc - p_w * 0.5f;
            const float py1 = pxc - p_h * 0.5f;
            const float px2 = pyc + p_w * 0.5f;
            const float py2 = pxc + p_h * 0.5f;
            const float area_p = (px2 - px1) * (py2 - py1);
            const float lx = fmaxf(px1, gx1);
            const float ly = fmaxf(py1, gy1);
            const float rx = fminf(px2, gx2);
            const float ry = fminf(py2, gy2);
            const float iw = fmaxf(rx - lx, 0.0f);
            const float ih = fmaxf(ry - ly, 0.0f);
            const float inter = iw * ih;
            res[(size_t)box * 5 + a] = __fdividef(inter, area_p + area_g - inter);
        }
    }
}

extern "C" void kernel_launch(void* const* d_in, const int* in_sizes, int n_in,
                              void* d_out, int out_size) {
    const int*   cell_nos = (const int*)d_in[0];
    const float* output   = (const float*)d_in[1];
    const float* target   = (const float*)d_in[2];
    float*       res      = (float*)d_out;

    const int n = in_sizes[0] / 2;  // cell_nos is [N,2]
    const int ntiles = n / BPB;
    int grid = (ntiles + 1) / 2;    // 2 tiles per CTA
    if (grid < 1) grid = 1;

    iou_kernel<<<grid, BPB>>>(cell_nos, output, target, res, n);
}

// round 15
// speedup vs baseline: 1.0609x; 1.0207x over previous
#include <cuda_runtime.h>
#include <cuda_bf16.h>
#include <cstdint>

// IoU kernel: elementwise over N boxes, A=5 anchors.
// Inputs (metadata order):
//   d_in[0]: cell_nos  int32  [N,2]
//   d_in[1]: output    float  [N,5,5]
//   d_in[2]: target    float  [N,5]
// Output: float [N,5]
//
// One-shot CTA swarm (R8 architecture), refined:
//  - stage holds only output+target (30720B) -> 7 CTAs/SM (vs 6 at 32KB):
//    +17% independent front-loaded TMA bursts per SM
//  - cell_nos loaded per-thread as int2 via __ldcs, issued BEFORE the mbar
//    wait so its latency hides under the TMA wait (only ~5% of traffic)
//  - early issue: t0 runs mbar init -> fence -> expect_tx -> bulk copies all
//    before __syncthreads (barrier off the load-issue path)
//  - results overwrite s_tgt in place; one bulk smem->gmem store per CTA.

#define YI 20.0f
#define BPB 256           // boxes per tile == threads per block
#define A 5               // anchors

#define OUT_BYTES (BPB * 25 * 4)   // 25600
#define TGT_BYTES (BPB * 5 * 4)    //  5120 (doubles as result buffer)
#define STAGE_BYTES (OUT_BYTES + TGT_BYTES)   // 30720

__global__ __launch_bounds__(BPB) void iou_kernel(
    const int2* __restrict__ cell_nos,
    const float* __restrict__ output,
    const float* __restrict__ target,
    float* __restrict__ res,
    int n)
{
    __shared__ alignas(16) float s_out[BPB * 25];   // 25600 B
    __shared__ alignas(16) float s_tgt[BPB * 5];    //  5120 B (result buffer too)
    __shared__ alignas(8)  unsigned long long mbar;

    const int tid  = threadIdx.x;
    const int base = blockIdx.x * BPB;
    const bool full = (base + BPB <= n);
    const int box  = base + tid;

    const uint32_t mbar_a = (uint32_t)__cvta_generic_to_shared(&mbar);
    const uint32_t so_a   = (uint32_t)__cvta_generic_to_shared(s_out);
    const uint32_t st_a   = (uint32_t)__cvta_generic_to_shared(s_tgt);

    if (full) {
        // Per-thread cell load, issued immediately: latency hides under the
        // TMA wait below. Coalesced 8B/thread streaming load.
        const int2 cell = __ldcs(&cell_nos[box]);

        // t0: init mbar, fence, and issue both bulk loads BEFORE the barrier.
        // (TMA completion targets the mbar t0 itself just initialized;
        // program order + the async fence make that safe.)
        if (tid == 0) {
            asm volatile("mbarrier.init.shared::cta.b64 [%0], 1;"
                         :: "r"(mbar_a) : "memory");
            asm volatile("fence.proxy.async.shared::cta;" ::: "memory");
            asm volatile("mbarrier.arrive.expect_tx.shared::cta.b64 _, [%0], %1;"
                         :: "r"(mbar_a), "r"((uint32_t)STAGE_BYTES) : "memory");
            asm volatile("cp.async.bulk.shared::cta.global.mbarrier::complete_tx::bytes "
                         "[%0], [%1], %2, [%3];"
                         :: "r"(so_a), "l"(output + (size_t)base * 25),
                            "r"((uint32_t)OUT_BYTES), "r"(mbar_a) : "memory");
            asm volatile("cp.async.bulk.shared::cta.global.mbarrier::complete_tx::bytes "
                         "[%0], [%1], %2, [%3];"
                         :: "r"(st_a), "l"(target + (size_t)base * 5),
                            "r"((uint32_t)TGT_BYTES), "r"(mbar_a) : "memory");
        }
        __syncthreads();   // mbar init visible to all threads before polling

        // Wait for TMA delivery (phase 0), acquire ordering for ld.shared.
        {
            uint32_t done;
            asm volatile(
                "{\n\t"
                ".reg .pred p;\n\t"
                "mbarrier.try_wait.parity.acquire.cta.shared::cta.b64 p, [%1], 0;\n\t"
                "selp.b32 %0, 1, 0, p;\n\t"
                "}"
                : "=r"(done) : "r"(mbar_a) : "memory");
            if (!done) {
                asm volatile(
                    "{\n\t"
                    ".reg .pred P1;\n\t"
                    "WAIT_LOOP_%=:\n\t"
                    "mbarrier.try_wait.parity.acquire.cta.shared::cta.b64 P1, [%0], 0, 0x989680;\n\t"
                    "@P1 bra.uni WAIT_DONE_%=;\n\t"
                    "bra.uni WAIT_LOOP_%=;\n\t"
                    "WAIT_DONE_%=:\n\t"
                    "}"
                    :: "r"(mbar_a) : "memory");
            }
        }

        // ---- compute; results overwrite s_tgt in place ----
        {
            const float ci = (float)cell.x * YI + YI * 0.5f;
            const float cj = (float)cell.y * YI + YI * 0.5f;

            const float* t = &s_tgt[5 * tid];
            const float g_h = t[3] * YI, g_w = t[4] * YI;
            const float gxc = ci + t[1] * YI;
            const float gyc = cj + t[2] * YI;
            const float gx1 = gyc - g_w * 0.5f;
            const float gy1 = gxc - g_h * 0.5f;
            const float gx2 = gyc + g_w * 0.5f;
            const float gy2 = gxc + g_h * 0.5f;
            const float area_g = (gx2 - gx1) * (gy2 - gy1);

            float r[A];
            #pragma unroll
            for (int a = 0; a < A; a++) {
                const float* o = &s_out[25 * tid + 5 * a];
                const float p_h = o[3] * YI, p_w = o[4] * YI;
                const float pxc = ci + o[1] * YI;
                const float pyc = cj + o[2] * YI;
                const float px1 = pyc - p_w * 0.5f;
                const float py1 = pxc - p_h * 0.5f;
                const float px2 = pyc + p_w * 0.5f;
                const float py2 = pxc + p_h * 0.5f;
                const float area_p = (px2 - px1) * (py2 - py1);

                const float lx = fmaxf(px1, gx1);
                const float ly = fmaxf(py1, gy1);
                const float rx = fminf(px2, gx2);
                const float ry = fminf(py2, gy2);
                const float iw = fmaxf(rx - lx, 0.0f);
                const float ih = fmaxf(ry - ly, 0.0f);
                const float inter = iw * ih;
                const float uni = area_p + area_g - inter;
                r[a] = __fdividef(inter, uni);
            }
            // Thread tid overwrites exactly [5*tid, 5*tid+5), which only it
            // read above -> no cross-thread hazard.
            #pragma unroll
            for (int a = 0; a < A; a++) s_tgt[5 * tid + a] = r[a];
        }
        __syncthreads();   // all results staged

        if (tid == 0) {
            asm volatile("fence.proxy.async.shared::cta;" ::: "memory");
            asm volatile("cp.async.bulk.global.shared::cta.bulk_group [%0], [%1], %2;"
                         :: "l"(res + (size_t)base * 5), "r"(st_a),
                            "r"((uint32_t)TGT_BYTES) : "memory");
            asm volatile("cp.async.bulk.commit_group;" ::: "memory");
            asm volatile("cp.async.bulk.wait_group 0;" ::: "memory");
        }
    } else if (box < n) {
        // Tail block (never taken at bench shape N=4,000,000=15625*256):
        // direct scalar path.
        const int2 cell = cell_nos[box];
        const float ci = (float)cell.x * YI + YI * 0.5f;
        const float cj = (float)cell.y * YI + YI * 0.5f;
        const float* t = target + (size_t)box * 5;
        const float g_h = t[3] * YI, g_w = t[4] * YI;
        const float gxc = ci + t[1] * YI;
        const float gyc = cj + t[2] * YI;
        const float gx1 = gyc - g_w * 0.5f;
        const float gy1 = gxc - g_h * 0.5f;
        const float gx2 = gyc + g_w * 0.5f;
        const float gy2 = gxc + g_h * 0.5f;
        const float area_g = (gx2 - gx1) * (gy2 - gy1);
        #pragma unroll
        for (int a = 0; a < A; a++) {
            const float* o = output + (size_t)box * 25 + 5 * a;
            const float p_h = o[3] * YI, p_w = o[4] * YI;
            const float pxc = ci + o[1] * YI;
            const float pyc = cj + o[2] * YI;
            const float px1 = pyc - p_w * 0.5f;
            const float py1 = pxc - p_h * 0.5f;
            const float px2 = pyc + p_w * 0.5f;
            const float py2 = pxc + p_h * 0.5f;
            const float area_p = (px2 - px1) * (py2 - py1);
            const float lx = fmaxf(px1, gx1);
            const float ly = fmaxf(py1, gy1);
            const float rx = fminf(px2, gx2);
            const float ry = fminf(py2, gy2);
            const float iw = fmaxf(rx - lx, 0.0f);
            const float ih = fmaxf(ry - ly, 0.0f);
            const float inter = iw * ih;
            res[(size_t)box * 5 + a] = __fdividef(inter, area_p + area_g - inter);
        }
    }
}

extern "C" void kernel_launch(void* const* d_in, const int* in_sizes, int n_in,
                              void* d_out, int out_size) {
    const int2*  cell_nos = (const int2*)d_in[0];
    const float* output   = (const float*)d_in[1];
    const float* target   = (const float*)d_in[2];
    float*       res      = (float*)d_out;

    const int n = in_sizes[0] / 2;  // cell_nos is [N,2]
    const int grid = (n + BPB - 1) / BPB;
    iou_kernel<<<grid, BPB>>>(cell_nos, output, target, res, n);
}